// round 3
// baseline (speedup 1.0000x reference)
#include <cuda_runtime.h>
#include <math.h>

#define B_MAX 4000000
#define P1_BLOCKS 1184     // 148 SMs * 8
#define P2_BLOCKS 1024
#define NTHREADS 256

__device__ float        g_dist[B_MAX];
__device__ unsigned int g_max_bits;
__device__ float        g_partials[P2_BLOCKS];

// ---------------------------------------------------------------------------
__global__ void k_init() {
    if (threadIdx.x == 0) g_max_bits = 0u;
}

// ---------------------------------------------------------------------------
// Pass 1: per-point ENU distance.
// Large-magnitude geodetic->ECEF path replicates the reference's f32 op
// sequence exactly; sin/cos are computed in f64 and rounded to f32, giving
// the CORRECTLY-ROUNDED f32 result (= CPU libm sinf/cosf bitwise).
__global__ void __launch_bounds__(NTHREADS)
k_pass1(const float* __restrict__ inp, const float* __restrict__ tgt, int B) {
    const float DEG2RAD = 0.017453292519943295f;   // f32(pi/180)
    const float E2      = 0.00669437999014f;
    const float A       = 6378137.0f;
    const float C1mE2   = 0.99330562000986f;       // f32(1.0 - E2), folded in f64

    float local_max = 0.0f;

    for (int i = blockIdx.x * blockDim.x + threadIdx.x; i < B;
         i += gridDim.x * blockDim.x) {
        float lat = tgt[3 * i + 0];
        float lon = tgt[3 * i + 1];
        float h   = tgt[3 * i + 2];

        float latr = __fmul_rn(lat, DEG2RAD);
        float lonr = __fmul_rn(lon, DEG2RAD);

        // correctly-rounded f32 trig via f64 (args are small: |x| <= pi)
        double slat_d, clat_d, slon_d, clon_d;
        sincos((double)latr, &slat_d, &clat_d);
        sincos((double)lonr, &slon_d, &clon_d);
        float sl = (float)slat_d, cl = (float)clat_d;
        float so = (float)slon_d, co = (float)clon_d;

        // t = 1 - ((E2*sl)*sl)  -- exact left-to-right association
        float t  = __fsub_rn(1.0f, __fmul_rn(__fmul_rn(E2, sl), sl));
        float N  = __fdiv_rn(A, __fsqrt_rn(t));
        float Nh = __fadd_rn(N, h);
        float Nhcl = __fmul_rn(Nh, cl);
        float rx = __fmul_rn(Nhcl, co);
        float ry = __fmul_rn(Nhcl, so);
        float rz = __fmul_rn(__fadd_rn(__fmul_rn(N, C1mE2), h), sl);

        // small-magnitude path: only relative accuracy matters here
        float dx = __fsub_rn(inp[3 * i + 0], rx);
        float dy = __fsub_rn(inp[3 * i + 1], ry);
        float dz = __fsub_rn(inp[3 * i + 2], rz);

        float e = -so * dx + co * dy;
        float n = -sl * co * dx - sl * so * dy + cl * dz;
        float u =  cl * co * dx + cl * so * dy + sl * dz;

        float dist = sqrtf(e * e + n * n + u * u);
        g_dist[i] = dist;
        local_max = fmaxf(local_max, dist);
    }

    // block max reduction
    __shared__ float smax[NTHREADS / 32];
    #pragma unroll
    for (int o = 16; o > 0; o >>= 1)
        local_max = fmaxf(local_max, __shfl_xor_sync(0xFFFFFFFFu, local_max, o));
    int lane = threadIdx.x & 31, wid = threadIdx.x >> 5;
    if (lane == 0) smax[wid] = local_max;
    __syncthreads();
    if (wid == 0) {
        float v = (lane < NTHREADS / 32) ? smax[lane] : 0.0f;
        #pragma unroll
        for (int o = 16; o > 0; o >>= 1)
            v = fmaxf(v, __shfl_xor_sync(0xFFFFFFFFu, v, o));
        if (lane == 0)
            atomicMax(&g_max_bits, __float_as_uint(v));  // dist >= 0: bit order == float order
    }
}

// ---------------------------------------------------------------------------
// Pass 2: focal loss squared, deterministic per-block partial sums.
__global__ void __launch_bounds__(NTHREADS)
k_pass2(int B) {
    float mx    = __uint_as_float(g_max_bits);
    float denom = __fadd_rn(mx, 1e-8f);

    float sum = 0.0f;
    for (int i = blockIdx.x * blockDim.x + threadIdx.x; i < B;
         i += gridDim.x * blockDim.x) {
        float d  = g_dist[i];
        float g  = 2.0f * expf(-d);                 // dynamic gamma (SCALE=1)
        float base = 1.0f - sqrtf(__fdiv_rn(d, denom));
        float w  = powf(base, g);
        float fl = w * d;                           // ALPHA = 1
        sum += fl * fl;
    }

    __shared__ float ssum[NTHREADS / 32];
    #pragma unroll
    for (int o = 16; o > 0; o >>= 1)
        sum += __shfl_xor_sync(0xFFFFFFFFu, sum, o);
    int lane = threadIdx.x & 31, wid = threadIdx.x >> 5;
    if (lane == 0) ssum[wid] = sum;
    __syncthreads();
    if (wid == 0) {
        float v = (lane < NTHREADS / 32) ? ssum[lane] : 0.0f;
        #pragma unroll
        for (int o = 16; o > 0; o >>= 1)
            v += __shfl_xor_sync(0xFFFFFFFFu, v, o);
        if (lane == 0) g_partials[blockIdx.x] = v;
    }
}

// ---------------------------------------------------------------------------
// Pass 3: final reduction of P2_BLOCKS partials.
__global__ void k_pass3(float* __restrict__ out, int B) {
    __shared__ float s[1024];
    int t = threadIdx.x;
    s[t] = (t < P2_BLOCKS) ? g_partials[t] : 0.0f;
    __syncthreads();
    for (int o = 512; o > 0; o >>= 1) {
        if (t < o) s[t] += s[t + o];
        __syncthreads();
    }
    if (t == 0) out[0] = sqrtf(s[0] / (float)B);
}

// ---------------------------------------------------------------------------
extern "C" void kernel_launch(void* const* d_in, const int* in_sizes, int n_in,
                              void* d_out, int out_size) {
    const float* inp = (const float*)d_in[0];   // (B,3) pred ECEF
    const float* tgt = (const float*)d_in[1];   // (B,3) lat/lon/h (deg, deg, m)
    int B = in_sizes[0] / 3;
    float* out = (float*)d_out;

    k_init<<<1, 32>>>();
    k_pass1<<<P1_BLOCKS, NTHREADS>>>(inp, tgt, B);
    k_pass2<<<P2_BLOCKS, NTHREADS>>>(B);
    k_pass3<<<1, 1024>>>(out, B);
}

// round 4
// speedup vs baseline: 6.6130x; 6.6130x over previous
#include <cuda_runtime.h>
#include <math.h>

#define B_MAX 4000000
#define P1_BLOCKS 1184     // 148 SMs * 8 (grid-stride)
#define P2_BLOCKS 1024
#define NTHREADS 256

__device__ float g_dist[B_MAX];
__device__ float g_blockmax[P1_BLOCKS];
__device__ float g_partials[P2_BLOCKS];

// ---------------------------------------------------------------------------
// Double-float sincos for |x| <= pi+eps. Produces f32 sin/cos with absolute
// error ~2^-31..2^-33, i.e. matching the correctly-rounded f32 result except
// on a <1% sliver of near-tie cases. ~25x cheaper than f64 sincos on B300's
// gimped FP64 pipe.
__device__ __forceinline__ void df_sincos(float x, float& s_out, float& c_out) {
    const float TWO_OVER_PI = 0.63661977236758134f;
    const float C1 = 1.57079637050628662109375f;   // float(pi/2)
    const float C2 = -4.37113900018624283e-8f;     // pi/2 - C1 (rounded)

    float qf = rintf(x * TWO_OVER_PI);             // q in {-2..2}
    int   n  = (int)qf;

    // r = x - q*pi/2 in double-float. q*C1 exact (q = 0,±1,±2).
    float a = fmaf(qf, -C1, x);                    // exact
    float b = -qf * C2;
    // TwoSum(a, b) (robust even when |a| < |b| near quadrant edges)
    float rhi = a + b;
    float bp  = rhi - a;
    float rlo = (a - (rhi - bp)) + (b - bp);

    // r^2 in double-float
    float r2h = rhi * rhi;
    float r2l = fmaf(rhi, rhi, -r2h);
    r2l = fmaf(rhi + rhi, rlo, r2l);

    // ---------------- sin(r) = r + r^3 * V(r^2) ----------------
    // V = -1/6 + r2/120 - r2^2/5040 + ... (Taylor through r^13)
    const float c13 =  1.60590438368216146e-10f;   //  1/6227020800
    const float c11 = -2.50521083854417202e-8f;    // -1/39916800
    const float c9  =  2.75573192239858907e-6f;    //  1/362880
    const float c7  = -1.98412698412698413e-4f;    // -1/5040
    const float c5  =  8.33333333333333333e-3f;    //  1/120
    const float c3h = -0.16666667163372039794921875f;  // float(-1/6)
    const float c3l =  4.96705424632835143e-9f;        // -1/6 - c3h

    float Q = fmaf(r2h, c13, c11);
    Q = fmaf(r2h, Q, c9);
    float T = fmaf(r2h, Q, c7);
    float U = fmaf(r2h, T, c5);
    // V = c3(df) + r2*U  (double-float)
    float ph = r2h * U;
    float pl = fmaf(r2h, U, -ph);
    pl = fmaf(r2l, U, pl);
    float vh = c3h + ph;                            // |c3h| >= |ph|
    float vl = ((c3h - vh) + ph) + pl + c3l;
    // w = r^3 in double-float: r2*rhi + r2h*rlo
    float wh = r2h * rhi;
    float wl = fmaf(r2h, rhi, -wh);
    wl = fmaf(r2l, rhi, wl);
    wl = fmaf(r2h, rlo, wl);
    // t = w*V
    float th = wh * vh;
    float tl = fmaf(wh, vh, -th);
    tl = fmaf(wh, vl, tl);
    tl = fmaf(wl, vh, tl);
    // sin = (rhi + rlo) + t   (|rhi| >= |th| always since |t|<=r^3/6)
    float sh = rhi + th;
    float sl = ((rhi - sh) + th) + tl + rlo;
    float sinr = sh + sl;

    // ---------------- cos(r) = (1 - r^2/2) + r^4 * E(r^2) ----------------
    // E = 1/24 - r2/720 + r2^2/40320 - r2^3/3628800 + r2^4/479001600
    const float e16 =  2.08767569878680990e-9f;    //  1/479001600
    const float e10 = -2.75573192239858907e-7f;    // -1/3628800
    const float e8  =  2.48015873015873016e-5f;    //  1/40320
    const float e6  = -1.38888888888888889e-3f;    // -1/720
    const float c4h =  0.041666667908430099487304688f; // float(1/24)
    const float c4l = -1.24176630587859679e-9f;        // 1/24 - c4h

    float F = fmaf(r2h, e16, e10);
    F = fmaf(r2h, F, e8);
    F = fmaf(r2h, F, e6);
    // E = c4(df) + r2*F
    float eh0 = r2h * F;
    float el0 = fmaf(r2h, F, -eh0);
    el0 = fmaf(r2l, F, el0);
    float Eh = c4h + eh0;                           // |c4h| >= |eh0|
    float El = ((c4h - Eh) + eh0) + el0 + c4l;
    // r^4 in double-float
    float r4h = r2h * r2h;
    float r4l = fmaf(r2h, r2h, -r4h);
    r4l = fmaf(r2h + r2h, r2l, r4l);
    // K = r4*E
    float kh = r4h * Eh;
    float kl = fmaf(r4h, Eh, -kh);
    kl = fmaf(r4h, El, kl);
    kl = fmaf(r4l, Eh, kl);
    // A = 1 - r2/2 (double-float, Fast2Sum exact: 1 >= r2h/2)
    float hh = 0.5f * r2h;
    float Ah = 1.0f - hh;
    float Al = (1.0f - Ah) - hh;
    Al = fmaf(-0.5f, r2l, Al);
    // cos = A + K   (|Ah| >= 0.69 > |kh|)
    float ch = Ah + kh;
    float cl = ((Ah - ch) + kh) + kl + Al;
    float cosr = ch + cl;

    // ---------------- quadrant fixup ----------------
    int m = n & 3;
    float s = (m & 1) ? cosr : sinr;
    float c = (m & 1) ? sinr : cosr;
    if (m & 2)       s = -s;
    if ((m + 1) & 2) c = -c;
    s_out = s;
    c_out = c;
}

// ---------------------------------------------------------------------------
// Pass 1: per-point ENU distance; large-magnitude geodetic->ECEF path
// replicates the reference's f32 op sequence exactly.
__global__ void __launch_bounds__(NTHREADS)
k_pass1(const float* __restrict__ inp, const float* __restrict__ tgt, int B) {
    const float DEG2RAD = 0.017453292519943295f;   // f32(pi/180)
    const float E2      = 0.00669437999014f;
    const float A       = 6378137.0f;
    const float C1mE2   = 0.99330562000986f;       // f32(1.0 - E2), folded in f64

    float local_max = 0.0f;

    for (int i = blockIdx.x * blockDim.x + threadIdx.x; i < B;
         i += gridDim.x * blockDim.x) {
        float lat = tgt[3 * i + 0];
        float lon = tgt[3 * i + 1];
        float h   = tgt[3 * i + 2];

        float latr = __fmul_rn(lat, DEG2RAD);
        float lonr = __fmul_rn(lon, DEG2RAD);

        float sl, cl, so, co;
        df_sincos(latr, sl, cl);
        df_sincos(lonr, so, co);

        // t = 1 - ((E2*sl)*sl)  -- exact left-to-right association
        float t  = __fsub_rn(1.0f, __fmul_rn(__fmul_rn(E2, sl), sl));
        float N  = __fdiv_rn(A, __fsqrt_rn(t));
        float Nh = __fadd_rn(N, h);
        float Nhcl = __fmul_rn(Nh, cl);
        float rx = __fmul_rn(Nhcl, co);
        float ry = __fmul_rn(Nhcl, so);
        float rz = __fmul_rn(__fadd_rn(__fmul_rn(N, C1mE2), h), sl);

        // small-magnitude path: only relative accuracy matters here
        float dx = __fsub_rn(inp[3 * i + 0], rx);
        float dy = __fsub_rn(inp[3 * i + 1], ry);
        float dz = __fsub_rn(inp[3 * i + 2], rz);

        float e = -so * dx + co * dy;
        float n = -sl * co * dx - sl * so * dy + cl * dz;
        float u =  cl * co * dx + cl * so * dy + sl * dz;

        float dist = sqrtf(e * e + n * n + u * u);
        g_dist[i] = dist;
        local_max = fmaxf(local_max, dist);
    }

    // block max -> per-block slot (no atomics, no init kernel)
    __shared__ float smax[NTHREADS / 32];
    #pragma unroll
    for (int o = 16; o > 0; o >>= 1)
        local_max = fmaxf(local_max, __shfl_xor_sync(0xFFFFFFFFu, local_max, o));
    int lane = threadIdx.x & 31, wid = threadIdx.x >> 5;
    if (lane == 0) smax[wid] = local_max;
    __syncthreads();
    if (wid == 0) {
        float v = (lane < NTHREADS / 32) ? smax[lane] : 0.0f;
        #pragma unroll
        for (int o = 16; o > 0; o >>= 1)
            v = fmaxf(v, __shfl_xor_sync(0xFFFFFFFFu, v, o));
        if (lane == 0) g_blockmax[blockIdx.x] = v;
    }
}

// ---------------------------------------------------------------------------
// Pass 2: reduce block maxima (exact max, order-independent), then focal loss
// squared with deterministic per-block partial sums.
__global__ void __launch_bounds__(NTHREADS)
k_pass2(int B) {
    // every block redundantly reduces the 1184 block maxima (L2-hot, cheap)
    float m = 0.0f;
    for (int i = threadIdx.x; i < P1_BLOCKS; i += NTHREADS)
        m = fmaxf(m, g_blockmax[i]);
    __shared__ float smax[NTHREADS / 32];
    #pragma unroll
    for (int o = 16; o > 0; o >>= 1)
        m = fmaxf(m, __shfl_xor_sync(0xFFFFFFFFu, m, o));
    int lane = threadIdx.x & 31, wid = threadIdx.x >> 5;
    if (lane == 0) smax[wid] = m;
    __syncthreads();
    if (wid == 0) {
        float v = (lane < NTHREADS / 32) ? smax[lane] : 0.0f;
        #pragma unroll
        for (int o = 16; o > 0; o >>= 1)
            v = fmaxf(v, __shfl_xor_sync(0xFFFFFFFFu, v, o));
        if (lane == 0) smax[0] = v;
    }
    __syncthreads();
    float denom = __fadd_rn(smax[0], 1e-8f);

    float sum = 0.0f;
    for (int i = blockIdx.x * blockDim.x + threadIdx.x; i < B;
         i += gridDim.x * blockDim.x) {
        float d  = g_dist[i];
        float g  = 2.0f * expf(-d);                 // dynamic gamma (SCALE=1)
        float base = 1.0f - sqrtf(__fdiv_rn(d, denom));
        float w  = powf(base, g);
        float fl = w * d;                           // ALPHA = 1
        sum += fl * fl;
    }

    __shared__ float ssum[NTHREADS / 32];
    #pragma unroll
    for (int o = 16; o > 0; o >>= 1)
        sum += __shfl_xor_sync(0xFFFFFFFFu, sum, o);
    if (lane == 0) ssum[wid] = sum;
    __syncthreads();
    if (wid == 0) {
        float v = (lane < NTHREADS / 32) ? ssum[lane] : 0.0f;
        #pragma unroll
        for (int o = 16; o > 0; o >>= 1)
            v += __shfl_xor_sync(0xFFFFFFFFu, v, o);
        if (lane == 0) g_partials[blockIdx.x] = v;
    }
}

// ---------------------------------------------------------------------------
__global__ void k_pass3(float* __restrict__ out, int B) {
    __shared__ float s[1024];
    int t = threadIdx.x;
    s[t] = (t < P2_BLOCKS) ? g_partials[t] : 0.0f;
    __syncthreads();
    for (int o = 512; o > 0; o >>= 1) {
        if (t < o) s[t] += s[t + o];
        __syncthreads();
    }
    if (t == 0) out[0] = sqrtf(s[0] / (float)B);
}

// ---------------------------------------------------------------------------
extern "C" void kernel_launch(void* const* d_in, const int* in_sizes, int n_in,
                              void* d_out, int out_size) {
    const float* inp = (const float*)d_in[0];   // (B,3) pred ECEF
    const float* tgt = (const float*)d_in[1];   // (B,3) lat/lon/h
    int B = in_sizes[0] / 3;
    float* out = (float*)d_out;

    k_pass1<<<P1_BLOCKS, NTHREADS>>>(inp, tgt, B);
    k_pass2<<<P2_BLOCKS, NTHREADS>>>(B);
    k_pass3<<<1, 1024>>>(out, B);
}

// round 5
// speedup vs baseline: 8.3145x; 1.2573x over previous
#include <cuda_runtime.h>
#include <math.h>

#define B_MAX 4000000
#define P1_BLOCKS 1184     // 148 SMs * 8 (grid-stride)
#define P2_BLOCKS 1024
#define NTHREADS 256

__device__ float        g_dist[B_MAX];
__device__ float        g_blockmax[P1_BLOCKS];
__device__ float        g_partials[P2_BLOCKS];
__device__ unsigned int g_ticket = 0;

// ---------------------------------------------------------------------------
// Double-float sincos for |x| <= pi+eps. f32 sin/cos with abs error ~2^-31,
// matching correctly-rounded f32 (CPU libm) except on a ~1% near-tie sliver.
__device__ __forceinline__ void df_sincos(float x, float& s_out, float& c_out) {
    const float TWO_OVER_PI = 0.63661977236758134f;
    const float C1 = 1.57079637050628662109375f;   // float(pi/2)
    const float C2 = -4.37113900018624283e-8f;     // pi/2 - C1 (rounded)

    float qf = rintf(x * TWO_OVER_PI);             // q in {-2..2}
    int   n  = (int)qf;

    float a = fmaf(qf, -C1, x);                    // exact
    float b = -qf * C2;
    float rhi = a + b;                             // TwoSum
    float bp  = rhi - a;
    float rlo = (a - (rhi - bp)) + (b - bp);

    float r2h = rhi * rhi;
    float r2l = fmaf(rhi, rhi, -r2h);
    r2l = fmaf(rhi + rhi, rlo, r2l);

    // ---- sin(r) = r + r^3 * V(r^2), V through r^13 ----
    const float c13 =  1.60590438368216146e-10f;
    const float c11 = -2.50521083854417202e-8f;
    const float c9  =  2.75573192239858907e-6f;
    const float c7  = -1.98412698412698413e-4f;
    const float c5  =  8.33333333333333333e-3f;
    const float c3h = -0.16666667163372039794921875f;
    const float c3l =  4.96705424632835143e-9f;

    float Q = fmaf(r2h, c13, c11);
    Q = fmaf(r2h, Q, c9);
    float T = fmaf(r2h, Q, c7);
    float U = fmaf(r2h, T, c5);
    float ph = r2h * U;
    float pl = fmaf(r2h, U, -ph);
    float vh = c3h + ph;
    float vl = ((c3h - vh) + ph) + pl + c3l;
    float wh = r2h * rhi;                          // r^3
    float wl = fmaf(r2h, rhi, -wh);
    wl = fmaf(r2h, rlo, wl);
    float th = wh * vh;
    float tl = fmaf(wh, vh, -th);
    tl = fmaf(wh, vl, tl);
    tl = fmaf(wl, vh, tl);
    float sh = rhi + th;
    float sl = ((rhi - sh) + th) + tl + rlo;
    float sinr = sh + sl;

    // ---- cos(r) = (1 - r^2/2) + r^4 * E(r^2) ----
    const float e16 =  2.08767569878680990e-9f;
    const float e10 = -2.75573192239858907e-7f;
    const float e8  =  2.48015873015873016e-5f;
    const float e6  = -1.38888888888888889e-3f;
    const float c4h =  0.041666667908430099487304688f;
    const float c4l = -1.24176630587859679e-9f;

    float F = fmaf(r2h, e16, e10);
    F = fmaf(r2h, F, e8);
    F = fmaf(r2h, F, e6);
    float eh0 = r2h * F;
    float el0 = fmaf(r2h, F, -eh0);
    float Eh = c4h + eh0;
    float El = ((c4h - Eh) + eh0) + el0 + c4l;
    float r4h = r2h * r2h;
    float kh = r4h * Eh;
    float kl = fmaf(r4h, Eh, -kh);
    kl = fmaf(r4h, El, kl);
    float hh = 0.5f * r2h;
    float Ah = 1.0f - hh;
    float Al = (1.0f - Ah) - hh;
    Al = fmaf(-0.5f, r2l, Al);
    float ch = Ah + kh;
    float cl = ((Ah - ch) + kh) + kl + Al;
    float cosr = ch + cl;

    int m = n & 3;
    float s = (m & 1) ? cosr : sinr;
    float c = (m & 1) ? sinr : cosr;
    if (m & 2)       s = -s;
    if ((m + 1) & 2) c = -c;
    s_out = s;
    c_out = c;
}

// ---------------------------------------------------------------------------
__device__ __forceinline__ float enu_dist(const float* __restrict__ inp,
                                          const float* __restrict__ tgt, int i) {
    const float DEG2RAD = 0.017453292519943295f;
    const float E2      = 0.00669437999014f;
    const float A       = 6378137.0f;
    const float C1mE2   = 0.99330562000986f;

    float lat = tgt[3 * i + 0];
    float lon = tgt[3 * i + 1];
    float h   = tgt[3 * i + 2];

    float latr = __fmul_rn(lat, DEG2RAD);
    float lonr = __fmul_rn(lon, DEG2RAD);

    float sl, cl, so, co;
    df_sincos(latr, sl, cl);
    df_sincos(lonr, so, co);

    // exact replication of reference f32 sequence (no FMA contraction)
    float t  = __fsub_rn(1.0f, __fmul_rn(__fmul_rn(E2, sl), sl));
    float N  = __fdiv_rn(A, __fsqrt_rn(t));
    float Nh = __fadd_rn(N, h);
    float Nhcl = __fmul_rn(Nh, cl);
    float rx = __fmul_rn(Nhcl, co);
    float ry = __fmul_rn(Nhcl, so);
    float rz = __fmul_rn(__fadd_rn(__fmul_rn(N, C1mE2), h), sl);

    float dx = __fsub_rn(inp[3 * i + 0], rx);
    float dy = __fsub_rn(inp[3 * i + 1], ry);
    float dz = __fsub_rn(inp[3 * i + 2], rz);

    float e = -so * dx + co * dy;
    float n = -sl * co * dx - sl * so * dy + cl * dz;
    float u =  cl * co * dx + cl * so * dy + sl * dz;

    return sqrtf(e * e + n * n + u * u);
}

// ---------------------------------------------------------------------------
// Pass 1: dist per point (stored), per-block max. 2-way unroll for ILP.
__global__ void __launch_bounds__(NTHREADS)
k_pass1(const float* __restrict__ inp, const float* __restrict__ tgt, int B) {
    int stride = gridDim.x * blockDim.x;
    int i0 = blockIdx.x * blockDim.x + threadIdx.x;
    float local_max = 0.0f;

    for (; i0 < B; i0 += 2 * stride) {
        int i1 = i0 + stride;
        float d0 = enu_dist(inp, tgt, i0);
        if (i1 < B) {
            float d1 = enu_dist(inp, tgt, i1);
            g_dist[i1] = d1;
            local_max = fmaxf(local_max, d1);
        }
        g_dist[i0] = d0;
        local_max = fmaxf(local_max, d0);
    }

    __shared__ float smax[NTHREADS / 32];
    #pragma unroll
    for (int o = 16; o > 0; o >>= 1)
        local_max = fmaxf(local_max, __shfl_xor_sync(0xFFFFFFFFu, local_max, o));
    int lane = threadIdx.x & 31, wid = threadIdx.x >> 5;
    if (lane == 0) smax[wid] = local_max;
    __syncthreads();
    if (wid == 0) {
        float v = (lane < NTHREADS / 32) ? smax[lane] : 0.0f;
        #pragma unroll
        for (int o = 16; o > 0; o >>= 1)
            v = fmaxf(v, __shfl_xor_sync(0xFFFFFFFFu, v, o));
        if (lane == 0) g_blockmax[blockIdx.x] = v;
    }
}

// ---------------------------------------------------------------------------
// Pass 2: reduce block maxima, focal-loss-squared partial sums; last block
// finishes the reduction (deterministic: fixed-order sum over g_partials).
__global__ void __launch_bounds__(NTHREADS)
k_pass2(float* __restrict__ out, int B) {
    // redundant per-block max reduction over 1184 slots (L2-hot)
    float m = 0.0f;
    for (int i = threadIdx.x; i < P1_BLOCKS; i += NTHREADS)
        m = fmaxf(m, g_blockmax[i]);
    __shared__ float smax[NTHREADS / 32];
    #pragma unroll
    for (int o = 16; o > 0; o >>= 1)
        m = fmaxf(m, __shfl_xor_sync(0xFFFFFFFFu, m, o));
    int lane = threadIdx.x & 31, wid = threadIdx.x >> 5;
    if (lane == 0) smax[wid] = m;
    __syncthreads();
    if (wid == 0) {
        float v = (lane < NTHREADS / 32) ? smax[lane] : 0.0f;
        #pragma unroll
        for (int o = 16; o > 0; o >>= 1)
            v = fmaxf(v, __shfl_xor_sync(0xFFFFFFFFu, v, o));
        if (lane == 0) smax[0] = v;
    }
    __syncthreads();
    float inv_denom = 1.0f / __fadd_rn(smax[0], 1e-8f);

    float sum = 0.0f;
    for (int i = blockIdx.x * blockDim.x + threadIdx.x; i < B;
         i += gridDim.x * blockDim.x) {
        float d    = g_dist[i];
        float g    = 2.0f * __expf(-d);                    // dyn gamma (MUFU)
        float base = 1.0f - sqrtf(d * inv_denom);          // base in (0,1]
        float w    = __expf(g * __logf(base));             // fast pow
        float fl   = w * d;
        sum += fl * fl;
    }

    __shared__ float ssum[NTHREADS / 32];
    #pragma unroll
    for (int o = 16; o > 0; o >>= 1)
        sum += __shfl_xor_sync(0xFFFFFFFFu, sum, o);
    if (lane == 0) ssum[wid] = sum;
    __syncthreads();
    if (wid == 0) {
        float v = (lane < NTHREADS / 32) ? ssum[lane] : 0.0f;
        #pragma unroll
        for (int o = 16; o > 0; o >>= 1)
            v += __shfl_xor_sync(0xFFFFFFFFu, v, o);
        if (lane == 0) g_partials[blockIdx.x] = v;
    }

    // ---- last block finishes ----
    __shared__ unsigned int s_ticket;
    __threadfence();
    if (threadIdx.x == 0)
        s_ticket = atomicAdd(&g_ticket, 1u);
    __syncthreads();
    if (s_ticket == P2_BLOCKS - 1) {
        // fixed-order (index-strided) sum: deterministic
        float fs = 0.0f;
        for (int i = threadIdx.x; i < P2_BLOCKS; i += NTHREADS)
            fs += g_partials[i];
        #pragma unroll
        for (int o = 16; o > 0; o >>= 1)
            fs += __shfl_xor_sync(0xFFFFFFFFu, fs, o);
        if (lane == 0) ssum[wid] = fs;
        __syncthreads();
        if (wid == 0) {
            float v = (lane < NTHREADS / 32) ? ssum[lane] : 0.0f;
            #pragma unroll
            for (int o = 16; o > 0; o >>= 1)
                v += __shfl_xor_sync(0xFFFFFFFFu, v, o);
            if (lane == 0) {
                out[0] = sqrtf(v / (float)B);
                g_ticket = 0;                    // reset for next graph replay
            }
        }
    }
}

// ---------------------------------------------------------------------------
extern "C" void kernel_launch(void* const* d_in, const int* in_sizes, int n_in,
                              void* d_out, int out_size) {
    const float* inp = (const float*)d_in[0];   // (B,3) pred ECEF
    const float* tgt = (const float*)d_in[1];   // (B,3) lat/lon/h
    int B = in_sizes[0] / 3;
    float* out = (float*)d_out;

    k_pass1<<<P1_BLOCKS, NTHREADS>>>(inp, tgt, B);
    k_pass2<<<P2_BLOCKS, NTHREADS>>>(out, B);
}

// round 6
// speedup vs baseline: 8.9373x; 1.0749x over previous
#include <cuda_runtime.h>
#include <math.h>

#define B_MAX    4000000
#define BLOCKS   592        // 148 SMs * 4, all co-resident (required for barrier)
#define NTHREADS 256
#define PTS_MAX  6784       // >= ceil(B_MAX / BLOCKS) = 6758

__device__ float             g_blockmax[BLOCKS];
__device__ float             g_partials[BLOCKS];
__device__ unsigned int      g_bar_count = 0;
__device__ volatile unsigned g_bar_flag  = 0;
__device__ unsigned int      g_ticket    = 0;

// ---------------------------------------------------------------------------
// Double-float sincos for |x| <= pi+eps. f32 sin/cos with abs error ~2^-31,
// matching correctly-rounded f32 (CPU libm) except on a tiny near-tie sliver.
__device__ __forceinline__ void df_sincos(float x, float& s_out, float& c_out) {
    const float TWO_OVER_PI = 0.63661977236758134f;
    const float C1 = 1.57079637050628662109375f;   // float(pi/2)
    const float C2 = -4.37113900018624283e-8f;     // pi/2 - C1 (rounded)

    float qf = rintf(x * TWO_OVER_PI);             // q in {-2..2}
    int   n  = (int)qf;

    float a = fmaf(qf, -C1, x);                    // exact
    float b = -qf * C2;
    float rhi = a + b;                             // TwoSum
    float bp  = rhi - a;
    float rlo = (a - (rhi - bp)) + (b - bp);

    float r2h = rhi * rhi;
    float r2l = fmaf(rhi, rhi, -r2h);
    r2l = fmaf(rhi + rhi, rlo, r2l);

    // ---- sin(r) = r + r^3 * V(r^2), V through r^13 ----
    const float c13 =  1.60590438368216146e-10f;
    const float c11 = -2.50521083854417202e-8f;
    const float c9  =  2.75573192239858907e-6f;
    const float c7  = -1.98412698412698413e-4f;
    const float c5  =  8.33333333333333333e-3f;
    const float c3h = -0.16666667163372039794921875f;
    const float c3l =  4.96705424632835143e-9f;

    float Q = fmaf(r2h, c13, c11);
    Q = fmaf(r2h, Q, c9);
    float T = fmaf(r2h, Q, c7);
    float U = fmaf(r2h, T, c5);
    float ph = r2h * U;
    float pl = fmaf(r2h, U, -ph);
    float vh = c3h + ph;
    float vl = ((c3h - vh) + ph) + pl + c3l;
    float wh = r2h * rhi;                          // r^3
    float wl = fmaf(r2h, rhi, -wh);
    wl = fmaf(r2h, rlo, wl);
    float th = wh * vh;
    float tl = fmaf(wh, vh, -th);
    tl = fmaf(wh, vl, tl);
    tl = fmaf(wl, vh, tl);
    float sh = rhi + th;
    float sl = ((rhi - sh) + th) + tl + rlo;
    float sinr = sh + sl;

    // ---- cos(r) = (1 - r^2/2) + r^4 * E(r^2) ----
    const float e16 =  2.08767569878680990e-9f;
    const float e10 = -2.75573192239858907e-7f;
    const float e8  =  2.48015873015873016e-5f;
    const float e6  = -1.38888888888888889e-3f;
    const float c4h =  0.041666667908430099487304688f;
    const float c4l = -1.24176630587859679e-9f;

    float F = fmaf(r2h, e16, e10);
    F = fmaf(r2h, F, e8);
    F = fmaf(r2h, F, e6);
    float eh0 = r2h * F;
    float el0 = fmaf(r2h, F, -eh0);
    float Eh = c4h + eh0;
    float El = ((c4h - Eh) + eh0) + el0 + c4l;
    float r4h = r2h * r2h;
    float kh = r4h * Eh;
    float kl = fmaf(r4h, Eh, -kh);
    kl = fmaf(r4h, El, kl);
    float hh = 0.5f * r2h;
    float Ah = 1.0f - hh;
    float Al = (1.0f - Ah) - hh;
    Al = fmaf(-0.5f, r2l, Al);
    float ch = Ah + kh;
    float cl = ((Ah - ch) + kh) + kl + Al;
    float cosr = ch + cl;

    int m = n & 3;
    float s = (m & 1) ? cosr : sinr;
    float c = (m & 1) ? sinr : cosr;
    if (m & 2)       s = -s;
    if ((m + 1) & 2) c = -c;
    s_out = s;
    c_out = c;
}

// ---------------------------------------------------------------------------
__device__ __forceinline__ float enu_dist(const float* __restrict__ inp,
                                          const float* __restrict__ tgt, int i) {
    const float DEG2RAD = 0.017453292519943295f;
    const float E2      = 0.00669437999014f;
    const float A       = 6378137.0f;
    const float C1mE2   = 0.99330562000986f;

    float lat = tgt[3 * i + 0];
    float lon = tgt[3 * i + 1];
    float h   = tgt[3 * i + 2];

    float latr = __fmul_rn(lat, DEG2RAD);
    float lonr = __fmul_rn(lon, DEG2RAD);

    float sl, cl, so, co;
    df_sincos(latr, sl, cl);
    df_sincos(lonr, so, co);

    // exact replication of reference f32 sequence (no FMA contraction)
    float t  = __fsub_rn(1.0f, __fmul_rn(__fmul_rn(E2, sl), sl));
    float N  = __fdiv_rn(A, __fsqrt_rn(t));
    float Nh = __fadd_rn(N, h);
    float Nhcl = __fmul_rn(Nh, cl);
    float rx = __fmul_rn(Nhcl, co);
    float ry = __fmul_rn(Nhcl, so);
    float rz = __fmul_rn(__fadd_rn(__fmul_rn(N, C1mE2), h), sl);

    float dx = __fsub_rn(inp[3 * i + 0], rx);
    float dy = __fsub_rn(inp[3 * i + 1], ry);
    float dz = __fsub_rn(inp[3 * i + 2], rz);

    float e = -so * dx + co * dy;
    float n = -sl * co * dx - sl * so * dy + cl * dz;
    float u =  cl * co * dx + cl * so * dy + sl * dz;

    return sqrtf(e * e + n * n + u * u);
}

// ---------------------------------------------------------------------------
// Fused persistent kernel: dist -> smem, grid barrier for global max, focal
// sum, deterministic last-block finish.
__global__ void __launch_bounds__(NTHREADS, 4)
k_fused(const float* __restrict__ inp, const float* __restrict__ tgt,
        float* __restrict__ out, int B) {
    __shared__ float s_dist[PTS_MAX];
    __shared__ float s_red[NTHREADS / 32];

    int chunk = (B + BLOCKS - 1) / BLOCKS;          // <= PTS_MAX
    int start = blockIdx.x * chunk;
    int cnt   = min(chunk, B - start);
    if (cnt < 0) cnt = 0;

    int lane = threadIdx.x & 31, wid = threadIdx.x >> 5;

    // ---------------- Phase 1: distances -> smem, block max ----------------
    float local_max = 0.0f;
    int k = threadIdx.x;
    for (; k + NTHREADS < cnt; k += 2 * NTHREADS) {   // 2-way unroll for ILP
        float d0 = enu_dist(inp, tgt, start + k);
        float d1 = enu_dist(inp, tgt, start + k + NTHREADS);
        s_dist[k] = d0;
        s_dist[k + NTHREADS] = d1;
        local_max = fmaxf(local_max, fmaxf(d0, d1));
    }
    if (k < cnt) {
        float d0 = enu_dist(inp, tgt, start + k);
        s_dist[k] = d0;
        local_max = fmaxf(local_max, d0);
    }

    #pragma unroll
    for (int o = 16; o > 0; o >>= 1)
        local_max = fmaxf(local_max, __shfl_xor_sync(0xFFFFFFFFu, local_max, o));
    if (lane == 0) s_red[wid] = local_max;
    __syncthreads();
    if (wid == 0) {
        float v = (lane < NTHREADS / 32) ? s_red[lane] : 0.0f;
        #pragma unroll
        for (int o = 16; o > 0; o >>= 1)
            v = fmaxf(v, __shfl_xor_sync(0xFFFFFFFFu, v, o));
        if (lane == 0) g_blockmax[blockIdx.x] = v;
    }

    // ---------------- Grid barrier (flag-flip, replay-safe) ----------------
    __threadfence();                                  // publish g_blockmax
    if (threadIdx.x == 0) {
        unsigned f = g_bar_flag;
        unsigned arrived = atomicAdd(&g_bar_count, 1u);
        if (arrived == BLOCKS - 1) {
            g_bar_count = 0;
            __threadfence();
            g_bar_flag = f ^ 1u;                      // release
        } else {
            while (g_bar_flag == f) { }               // spin (volatile)
        }
    }
    __syncthreads();
    __threadfence();                                  // acquire

    // ---------------- Global max (every block, fixed order) ----------------
    float m = 0.0f;
    for (int i = threadIdx.x; i < BLOCKS; i += NTHREADS)
        m = fmaxf(m, g_blockmax[i]);
    #pragma unroll
    for (int o = 16; o > 0; o >>= 1)
        m = fmaxf(m, __shfl_xor_sync(0xFFFFFFFFu, m, o));
    if (lane == 0) s_red[wid] = m;
    __syncthreads();
    if (wid == 0) {
        float v = (lane < NTHREADS / 32) ? s_red[lane] : 0.0f;
        #pragma unroll
        for (int o = 16; o > 0; o >>= 1)
            v = fmaxf(v, __shfl_xor_sync(0xFFFFFFFFu, v, o));
        if (lane == 0) s_red[0] = v;
    }
    __syncthreads();
    float inv_denom = 1.0f / __fadd_rn(s_red[0], 1e-8f);
    __syncthreads();                                  // s_red reused below

    // ---------------- Phase 2: focal loss from smem ----------------
    float sum = 0.0f;
    for (int i = threadIdx.x; i < cnt; i += NTHREADS) {
        float d    = s_dist[i];
        float g    = 2.0f * __expf(-d);               // dynamic gamma (MUFU)
        float base = 1.0f - sqrtf(d * inv_denom);
        float w    = __expf(g * __logf(base));        // fast pow
        float fl   = w * d;
        sum += fl * fl;
    }

    #pragma unroll
    for (int o = 16; o > 0; o >>= 1)
        sum += __shfl_xor_sync(0xFFFFFFFFu, sum, o);
    if (lane == 0) s_red[wid] = sum;
    __syncthreads();
    if (wid == 0) {
        float v = (lane < NTHREADS / 32) ? s_red[lane] : 0.0f;
        #pragma unroll
        for (int o = 16; o > 0; o >>= 1)
            v += __shfl_xor_sync(0xFFFFFFFFu, v, o);
        if (lane == 0) g_partials[blockIdx.x] = v;
    }

    // ---------------- Last block finishes (deterministic) ----------------
    __shared__ unsigned s_ticket;
    __threadfence();
    if (threadIdx.x == 0)
        s_ticket = atomicAdd(&g_ticket, 1u);
    __syncthreads();
    if (s_ticket == BLOCKS - 1) {
        __threadfence();
        float fs = 0.0f;
        for (int i = threadIdx.x; i < BLOCKS; i += NTHREADS)
            fs += g_partials[i];                      // fixed index order
        #pragma unroll
        for (int o = 16; o > 0; o >>= 1)
            fs += __shfl_xor_sync(0xFFFFFFFFu, fs, o);
        __syncthreads();                              // s_red reuse
        if (lane == 0) s_red[wid] = fs;
        __syncthreads();
        if (wid == 0) {
            float v = (lane < NTHREADS / 32) ? s_red[lane] : 0.0f;
            #pragma unroll
            for (int o = 16; o > 0; o >>= 1)
                v += __shfl_xor_sync(0xFFFFFFFFu, v, o);
            if (lane == 0) {
                out[0] = sqrtf(v / (float)B);
                g_ticket = 0;                         // reset for next replay
            }
        }
    }
}

// ---------------------------------------------------------------------------
extern "C" void kernel_launch(void* const* d_in, const int* in_sizes, int n_in,
                              void* d_out, int out_size) {
    const float* inp = (const float*)d_in[0];   // (B,3) pred ECEF
    const float* tgt = (const float*)d_in[1];   // (B,3) lat/lon/h
    int B = in_sizes[0] / 3;
    float* out = (float*)d_out;

    k_fused<<<BLOCKS, NTHREADS>>>(inp, tgt, out, B);
}

// round 7
// speedup vs baseline: 8.9430x; 1.0006x over previous
#include <cuda_runtime.h>
#include <math.h>

#define B_MAX    4000000
#define BLOCKS   740        // 148 SMs * 5, all co-resident (required for barrier)
#define NTHREADS 256
#define PTS_MAX  5408       // >= ceil(B_MAX / BLOCKS) = 5406

__device__ float             g_blockmax[BLOCKS];
__device__ float             g_partials[BLOCKS];
__device__ unsigned int      g_bar_count = 0;
__device__ volatile unsigned g_bar_flag  = 0;
__device__ unsigned int      g_ticket    = 0;

// ---------------------------------------------------------------------------
// Double-float sincos for |x| <= pi+eps. f32 sin/cos with abs error ~2^-31,
// matching correctly-rounded f32 (CPU libm) except on a tiny near-tie sliver.
__device__ __forceinline__ void df_sincos(float x, float& s_out, float& c_out) {
    const float TWO_OVER_PI = 0.63661977236758134f;
    const float C1 = 1.57079637050628662109375f;   // float(pi/2)
    const float C2 = -4.37113900018624283e-8f;     // pi/2 - C1 (rounded)

    float qf = rintf(x * TWO_OVER_PI);             // q in {-2..2}
    int   n  = (int)qf;

    float a = fmaf(qf, -C1, x);                    // exact
    float b = -qf * C2;
    float rhi = a + b;                             // TwoSum
    float bp  = rhi - a;
    float rlo = (a - (rhi - bp)) + (b - bp);

    float r2h = rhi * rhi;
    float r2l = fmaf(rhi, rhi, -r2h);
    r2l = fmaf(rhi + rhi, rlo, r2l);

    // ---- sin(r) = r + r^3 * V(r^2), V through r^11 ----
    const float c11 = -2.50521083854417202e-8f;
    const float c9  =  2.75573192239858907e-6f;
    const float c7  = -1.98412698412698413e-4f;
    const float c5  =  8.33333333333333333e-3f;
    const float c3h = -0.16666667163372039794921875f;
    const float c3l =  4.96705424632835143e-9f;

    float Q = fmaf(r2h, c11, c9);
    float T = fmaf(r2h, Q, c7);
    float U = fmaf(r2h, T, c5);
    float ph = r2h * U;
    float pl = fmaf(r2h, U, -ph);
    float vh = c3h + ph;
    float vl = ((c3h - vh) + ph) + pl + c3l;
    float wh = r2h * rhi;                          // r^3
    float wl = fmaf(r2h, rhi, -wh);
    wl = fmaf(r2h, rlo, wl);
    float th = wh * vh;
    float tl = fmaf(wh, vh, -th);
    tl = fmaf(wh, vl, tl);
    tl = fmaf(wl, vh, tl);
    float sh = rhi + th;
    float sl = ((rhi - sh) + th) + tl + rlo;
    float sinr = sh + sl;

    // ---- cos(r) = (1 - r^2/2) + r^4 * E(r^2) ----
    const float e16 =  2.08767569878680990e-9f;
    const float e10 = -2.75573192239858907e-7f;
    const float e8  =  2.48015873015873016e-5f;
    const float e6  = -1.38888888888888889e-3f;
    const float c4h =  0.041666667908430099487304688f;
    const float c4l = -1.24176630587859679e-9f;

    float F = fmaf(r2h, e16, e10);
    F = fmaf(r2h, F, e8);
    F = fmaf(r2h, F, e6);
    float eh0 = r2h * F;
    float el0 = fmaf(r2h, F, -eh0);
    float Eh = c4h + eh0;
    float El = ((c4h - Eh) + eh0) + el0 + c4l;
    float r4h = r2h * r2h;
    float kh = r4h * Eh;
    float kl = fmaf(r4h, Eh, -kh);
    kl = fmaf(r4h, El, kl);
    float hh = 0.5f * r2h;
    float Ah = 1.0f - hh;
    float Al = (1.0f - Ah) - hh;
    Al = fmaf(-0.5f, r2l, Al);
    float ch = Ah + kh;
    float cl = ((Ah - ch) + kh) + kl + Al;
    float cosr = ch + cl;

    int m = n & 3;
    float s = (m & 1) ? cosr : sinr;
    float c = (m & 1) ? sinr : cosr;
    if (m & 2)       s = -s;
    if ((m + 1) & 2) c = -c;
    s_out = s;
    c_out = c;
}

// ---------------------------------------------------------------------------
__device__ __forceinline__ float enu_dist(const float* __restrict__ inp,
                                          const float* __restrict__ tgt, int i) {
    const float DEG2RAD = 0.017453292519943295f;
    const float E2      = 0.00669437999014f;
    const float A       = 6378137.0f;
    const float C1mE2   = 0.99330562000986f;

    float lat = tgt[3 * i + 0];
    float lon = tgt[3 * i + 1];
    float h   = tgt[3 * i + 2];

    float latr = __fmul_rn(lat, DEG2RAD);
    float lonr = __fmul_rn(lon, DEG2RAD);

    float sl, cl, so, co;
    df_sincos(latr, sl, cl);
    df_sincos(lonr, so, co);

    // exact replication of reference f32 sequence (no FMA contraction)
    float t  = __fsub_rn(1.0f, __fmul_rn(__fmul_rn(E2, sl), sl));
    float N  = __fdiv_rn(A, __fsqrt_rn(t));
    float Nh = __fadd_rn(N, h);
    float Nhcl = __fmul_rn(Nh, cl);
    float rx = __fmul_rn(Nhcl, co);
    float ry = __fmul_rn(Nhcl, so);
    float rz = __fmul_rn(__fadd_rn(__fmul_rn(N, C1mE2), h), sl);

    float dx = __fsub_rn(inp[3 * i + 0], rx);
    float dy = __fsub_rn(inp[3 * i + 1], ry);
    float dz = __fsub_rn(inp[3 * i + 2], rz);

    float e = -so * dx + co * dy;
    float n = -sl * co * dx - sl * so * dy + cl * dz;
    float u =  cl * co * dx + cl * so * dy + sl * dz;

    return sqrtf(e * e + n * n + u * u);
}

// ---------------------------------------------------------------------------
// Fused persistent kernel: dist -> smem, grid barrier for global max, focal
// sum, deterministic last-block finish.
__global__ void __launch_bounds__(NTHREADS, 5)
k_fused(const float* __restrict__ inp, const float* __restrict__ tgt,
        float* __restrict__ out, int B) {
    __shared__ float s_dist[PTS_MAX];
    __shared__ float s_red[NTHREADS / 32];

    int chunk = (B + BLOCKS - 1) / BLOCKS;          // <= PTS_MAX
    int start = blockIdx.x * chunk;
    int cnt   = min(chunk, B - start);
    if (cnt < 0) cnt = 0;

    int lane = threadIdx.x & 31, wid = threadIdx.x >> 5;

    // ---------------- Phase 1: distances -> smem, block max ----------------
    float local_max = 0.0f;
    int k = threadIdx.x;
    for (; k + NTHREADS < cnt; k += 2 * NTHREADS) {   // 2-way unroll for ILP
        float d0 = enu_dist(inp, tgt, start + k);
        float d1 = enu_dist(inp, tgt, start + k + NTHREADS);
        s_dist[k] = d0;
        s_dist[k + NTHREADS] = d1;
        local_max = fmaxf(local_max, fmaxf(d0, d1));
    }
    if (k < cnt) {
        float d0 = enu_dist(inp, tgt, start + k);
        s_dist[k] = d0;
        local_max = fmaxf(local_max, d0);
    }

    #pragma unroll
    for (int o = 16; o > 0; o >>= 1)
        local_max = fmaxf(local_max, __shfl_xor_sync(0xFFFFFFFFu, local_max, o));
    if (lane == 0) s_red[wid] = local_max;
    __syncthreads();
    if (wid == 0) {
        float v = (lane < NTHREADS / 32) ? s_red[lane] : 0.0f;
        #pragma unroll
        for (int o = 16; o > 0; o >>= 1)
            v = fmaxf(v, __shfl_xor_sync(0xFFFFFFFFu, v, o));
        if (lane == 0) g_blockmax[blockIdx.x] = v;
    }

    // ---------------- Grid barrier (flag-flip, replay-safe) ----------------
    __threadfence();                                  // publish g_blockmax
    if (threadIdx.x == 0) {
        unsigned f = g_bar_flag;
        unsigned arrived = atomicAdd(&g_bar_count, 1u);
        if (arrived == BLOCKS - 1) {
            g_bar_count = 0;
            __threadfence();
            g_bar_flag = f ^ 1u;                      // release
        } else {
            while (g_bar_flag == f) { }               // spin (volatile)
        }
    }
    __syncthreads();
    __threadfence();                                  // acquire

    // ---------------- Global max (every block, fixed order) ----------------
    float m = 0.0f;
    for (int i = threadIdx.x; i < BLOCKS; i += NTHREADS)
        m = fmaxf(m, g_blockmax[i]);
    #pragma unroll
    for (int o = 16; o > 0; o >>= 1)
        m = fmaxf(m, __shfl_xor_sync(0xFFFFFFFFu, m, o));
    if (lane == 0) s_red[wid] = m;
    __syncthreads();
    if (wid == 0) {
        float v = (lane < NTHREADS / 32) ? s_red[lane] : 0.0f;
        #pragma unroll
        for (int o = 16; o > 0; o >>= 1)
            v = fmaxf(v, __shfl_xor_sync(0xFFFFFFFFu, v, o));
        if (lane == 0) s_red[0] = v;
    }
    __syncthreads();
    float inv_denom = 1.0f / __fadd_rn(s_red[0], 1e-8f);
    __syncthreads();                                  // s_red reused below

    // ---------------- Phase 2: focal loss from smem ----------------
    float sum = 0.0f;
    for (int i = threadIdx.x; i < cnt; i += NTHREADS) {
        float d    = s_dist[i];
        float g    = 2.0f * __expf(-d);               // dynamic gamma (MUFU)
        float base = 1.0f - sqrtf(d * inv_denom);
        float w    = __expf(g * __logf(base));        // fast pow
        float fl   = w * d;
        sum += fl * fl;
    }

    #pragma unroll
    for (int o = 16; o > 0; o >>= 1)
        sum += __shfl_xor_sync(0xFFFFFFFFu, sum, o);
    if (lane == 0) s_red[wid] = sum;
    __syncthreads();
    if (wid == 0) {
        float v = (lane < NTHREADS / 32) ? s_red[lane] : 0.0f;
        #pragma unroll
        for (int o = 16; o > 0; o >>= 1)
            v += __shfl_xor_sync(0xFFFFFFFFu, v, o);
        if (lane == 0) g_partials[blockIdx.x] = v;
    }

    // ---------------- Last block finishes (deterministic) ----------------
    __shared__ unsigned s_ticket;
    __threadfence();
    if (threadIdx.x == 0)
        s_ticket = atomicAdd(&g_ticket, 1u);
    __syncthreads();
    if (s_ticket == BLOCKS - 1) {
        __threadfence();
        float fs = 0.0f;
        for (int i = threadIdx.x; i < BLOCKS; i += NTHREADS)
            fs += g_partials[i];                      // fixed index order
        #pragma unroll
        for (int o = 16; o > 0; o >>= 1)
            fs += __shfl_xor_sync(0xFFFFFFFFu, fs, o);
        __syncthreads();                              // s_red reuse
        if (lane == 0) s_red[wid] = fs;
        __syncthreads();
        if (wid == 0) {
            float v = (lane < NTHREADS / 32) ? s_red[lane] : 0.0f;
            #pragma unroll
            for (int o = 16; o > 0; o >>= 1)
                v += __shfl_xor_sync(0xFFFFFFFFu, v, o);
            if (lane == 0) {
                out[0] = sqrtf(v / (float)B);
                g_ticket = 0;                         // reset for next replay
            }
        }
    }
}

// ---------------------------------------------------------------------------
extern "C" void kernel_launch(void* const* d_in, const int* in_sizes, int n_in,
                              void* d_out, int out_size) {
    const float* inp = (const float*)d_in[0];   // (B,3) pred ECEF
    const float* tgt = (const float*)d_in[1];   // (B,3) lat/lon/h
    int B = in_sizes[0] / 3;
    float* out = (float*)d_out;

    k_fused<<<BLOCKS, NTHREADS>>>(inp, tgt, out, B);
}